// round 1
// baseline (speedup 1.0000x reference)
#include <cuda_runtime.h>
#include <math.h>
#include <float.h>

#define BB 4
#define SS 2048
#define DD 1024

// Scratch (static device allocations are permitted; runtime allocs are not)
__device__ float g_q[BB * SS * DD];                 // 32 MB
__device__ float g_k[BB * SS * DD];                 // 32 MB
__device__ float g_v[BB * SS * DD];                 // 32 MB
__device__ float g_sc[(size_t)BB * SS * SS];        // 64 MB scores

// ---------------------------------------------------------------------------
// Kernel 1: Givens-rotate Q into q,k,v (one thread per column pair)
// ---------------------------------------------------------------------------
__global__ void prep_kernel(const float* __restrict__ Q,
                            const float* __restrict__ rot_w) {
    int idx = blockIdx.x * blockDim.x + threadIdx.x;   // pair index
    int total = BB * SS * (DD / 2);
    if (idx >= total) return;
    int p = idx % (DD / 2);
    long base = (long)(idx / (DD / 2)) * DD;           // row base (b,s)
    float x0 = Q[base + 2 * p];
    float x1 = Q[base + 2 * p + 1];
#pragma unroll
    for (int r = 0; r < 3; r++) {
        float c = rot_w[r * DD + 2 * p];
        float s = rot_w[r * DD + 2 * p + 1];
        float inv = rsqrtf(c * c + s * s);
        c *= inv; s *= inv;
        float y0 = c * x0 - s * x1;
        float y1 = c * x1 + s * x0;
        float* dst = (r == 0) ? g_q : (r == 1) ? g_k : g_v;
        dst[base + 2 * p]     = y0;
        dst[base + 2 * p + 1] = y1;
    }
}

// ---------------------------------------------------------------------------
// Register-tiled fp32 GEMM body.  BM=128, BN=64, BK=32, 256 threads, 8x4 micro.
// BTRANS=true : C[i][j] = sum_k A[i][k] * B[j][k]   (NT, for q @ k^T)
// BTRANS=false: C[i][j] = sum_k A[i][k] * B[k][j]   (NN, for P @ v)
// ---------------------------------------------------------------------------
constexpr int BM = 128, BN = 64, BK = 32, TM = 8, TN = 4;

template <bool BTRANS>
__device__ __forceinline__ void gemm_body(const float* __restrict__ A,
                                          const float* __restrict__ Bm,
                                          float* __restrict__ C,
                                          int K, int lda, int ldb, int ldc) {
    __shared__ float As[BK][BM];
    __shared__ float Bs[BK][BN];

    int m0 = blockIdx.y * BM;
    int n0 = blockIdx.x * BN;
    int tid = threadIdx.x;
    int ty = tid / 16;   // 0..15  -> rows ty*8..ty*8+7
    int tx = tid % 16;   // 0..15  -> cols tx*4..tx*4+3

    float acc[TM][TN] = {};

    for (int k0 = 0; k0 < K; k0 += BK) {
        // --- load A tile (BM x BK), store transposed As[kk][r] ---
#pragma unroll
        for (int i = 0; i < 4; i++) {
            int l = tid + i * 256;           // float4 index, 0..1023
            int r = l >> 3;                  // /(BK/4)
            int kk = (l & 7) * 4;
            float4 va = *(const float4*)(A + (long)(m0 + r) * lda + k0 + kk);
            As[kk + 0][r] = va.x;
            As[kk + 1][r] = va.y;
            As[kk + 2][r] = va.z;
            As[kk + 3][r] = va.w;
        }
        // --- load B tile ---
        if (BTRANS) {
#pragma unroll
            for (int i = 0; i < 2; i++) {
                int l = tid + i * 256;       // 0..511
                int c = l >> 3;
                int kk = (l & 7) * 4;
                float4 vb = *(const float4*)(Bm + (long)(n0 + c) * ldb + k0 + kk);
                Bs[kk + 0][c] = vb.x;
                Bs[kk + 1][c] = vb.y;
                Bs[kk + 2][c] = vb.z;
                Bs[kk + 3][c] = vb.w;
            }
        } else {
#pragma unroll
            for (int i = 0; i < 2; i++) {
                int l = tid + i * 256;       // 0..511
                int kk = l >> 4;             // /(BN/4)
                int c = (l & 15) * 4;
                float4 vb = *(const float4*)(Bm + (long)(k0 + kk) * ldb + n0 + c);
                *(float4*)&Bs[kk][c] = vb;
            }
        }
        __syncthreads();

#pragma unroll
        for (int kk = 0; kk < BK; kk++) {
            float a[TM], b[TN];
            const float4* ap = (const float4*)&As[kk][ty * TM];
            float4 a0 = ap[0], a1 = ap[1];
            a[0] = a0.x; a[1] = a0.y; a[2] = a0.z; a[3] = a0.w;
            a[4] = a1.x; a[5] = a1.y; a[6] = a1.z; a[7] = a1.w;
            float4 b0 = *(const float4*)&Bs[kk][tx * TN];
            b[0] = b0.x; b[1] = b0.y; b[2] = b0.z; b[3] = b0.w;
#pragma unroll
            for (int i = 0; i < TM; i++)
#pragma unroll
                for (int j = 0; j < TN; j++)
                    acc[i][j] = fmaf(a[i], b[j], acc[i][j]);
        }
        __syncthreads();
    }

#pragma unroll
    for (int i = 0; i < TM; i++) {
        float4 vo = make_float4(acc[i][0], acc[i][1], acc[i][2], acc[i][3]);
        *(float4*)(C + (long)(m0 + ty * TM + i) * ldc + n0 + tx * TN) = vo;
    }
}

__global__ __launch_bounds__(256) void gemm_qk_kernel() {
    const float* A = g_q + (long)blockIdx.z * SS * DD;
    const float* Bm = g_k + (long)blockIdx.z * SS * DD;
    float* C = g_sc + (size_t)blockIdx.z * SS * SS;
    gemm_body<true>(A, Bm, C, DD, DD, DD, SS);
}

__global__ __launch_bounds__(256) void gemm_pv_kernel(float* __restrict__ out) {
    const float* A = g_sc + (size_t)blockIdx.z * SS * SS;
    const float* Bm = g_v + (long)blockIdx.z * SS * DD;
    float* C = out + (long)blockIdx.z * SS * DD;
    gemm_body<false>(A, Bm, C, SS, SS, DD, DD);
}

// ---------------------------------------------------------------------------
// Row softmax over scores with affine transform t = (2 + 2x)/scale + bias
// One block (256 threads) per row of length S=2048.
// ---------------------------------------------------------------------------
__global__ __launch_bounds__(256) void softmax_kernel(const float* __restrict__ scale,
                                                      const float* __restrict__ bias) {
    float* row = g_sc + (size_t)blockIdx.x * SS;
    float scl = scale[0];
    float bs = bias[0];
    int tid = threadIdx.x;

    float vals[8];
    float lmax = -FLT_MAX;
#pragma unroll
    for (int i = 0; i < 8; i++) {
        float x = row[tid + i * 256];
        float t = fmaf(2.0f, x, 2.0f) / scl + bs;
        vals[i] = t;
        lmax = fmaxf(lmax, t);
    }

    __shared__ float sred[8];
    __shared__ float sbc;
    // block max
    float v = lmax;
#pragma unroll
    for (int o = 16; o > 0; o >>= 1) v = fmaxf(v, __shfl_xor_sync(0xffffffffu, v, o));
    if ((tid & 31) == 0) sred[tid >> 5] = v;
    __syncthreads();
    if (tid == 0) {
        float m = sred[0];
#pragma unroll
        for (int i = 1; i < 8; i++) m = fmaxf(m, sred[i]);
        sbc = m;
    }
    __syncthreads();
    float m = sbc;

    float lsum = 0.0f;
#pragma unroll
    for (int i = 0; i < 8; i++) {
        vals[i] = __expf(vals[i] - m);
        lsum += vals[i];
    }
    v = lsum;
#pragma unroll
    for (int o = 16; o > 0; o >>= 1) v += __shfl_xor_sync(0xffffffffu, v, o);
    __syncthreads();   // protect sred reuse
    if ((tid & 31) == 0) sred[tid >> 5] = v;
    __syncthreads();
    if (tid == 0) {
        float t = 0.0f;
#pragma unroll
        for (int i = 0; i < 8; i++) t += sred[i];
        sbc = 1.0f / t;
    }
    __syncthreads();
    float inv = sbc;
#pragma unroll
    for (int i = 0; i < 8; i++) row[tid + i * 256] = vals[i] * inv;
}

// ---------------------------------------------------------------------------
// Row L2 normalization: out = ave * rsqrt(clip(|sum ave^2|, 1e-8))
// One block (256 threads) per row of length D=1024.
// ---------------------------------------------------------------------------
__global__ __launch_bounds__(256) void normalize_kernel(float* __restrict__ out) {
    float* row = out + (long)blockIdx.x * DD;
    int tid = threadIdx.x;
    float v[4];
    float ss = 0.0f;
#pragma unroll
    for (int i = 0; i < 4; i++) {
        v[i] = row[tid + i * 256];
        ss = fmaf(v[i], v[i], ss);
    }
    __shared__ float sred[8];
    __shared__ float sbc;
    float r = ss;
#pragma unroll
    for (int o = 16; o > 0; o >>= 1) r += __shfl_xor_sync(0xffffffffu, r, o);
    if ((tid & 31) == 0) sred[tid >> 5] = r;
    __syncthreads();
    if (tid == 0) {
        float t = 0.0f;
#pragma unroll
        for (int i = 0; i < 8; i++) t += sred[i];
        sbc = rsqrtf(fmaxf(fabsf(t), 1e-8f));
    }
    __syncthreads();
    float inv = sbc;
#pragma unroll
    for (int i = 0; i < 4; i++) row[tid + i * 256] = v[i] * inv;
}

// ---------------------------------------------------------------------------
extern "C" void kernel_launch(void* const* d_in, const int* in_sizes, int n_in,
                              void* d_out, int out_size) {
    (void)in_sizes; (void)n_in; (void)out_size;
    const float* Q     = (const float*)d_in[0];
    const float* rot_w = (const float*)d_in[1];
    const float* scale = (const float*)d_in[2];
    const float* bias  = (const float*)d_in[3];
    float* out = (float*)d_out;

    // 1) rotate
    int pairs = BB * SS * (DD / 2);
    prep_kernel<<<(pairs + 255) / 256, 256>>>(Q, rot_w);

    // 2) scores = q @ k^T  (per batch 2048x2048x1024, NT)
    dim3 g1(SS / BN, SS / BM, BB);
    gemm_qk_kernel<<<g1, 256>>>();

    // 3) softmax rows
    softmax_kernel<<<BB * SS, 256>>>(scale, bias);

    // 4) out = P @ v  (per batch 2048x1024x2048, NN)
    dim3 g2(DD / BN, SS / BM, BB);
    gemm_pv_kernel<<<g2, 256>>>(out);

    // 5) normalize rows
    normalize_kernel<<<BB * SS, 256>>>(out);
}

// round 3
// speedup vs baseline: 1.6565x; 1.6565x over previous
#include <cuda_runtime.h>
#include <cuda_fp16.h>
#include <math.h>
#include <float.h>
#include <stdint.h>

#define BB 4
#define SS 2048
#define DD 1024

// ---------------------------------------------------------------------------
// Scratch (static device globals; runtime allocation is forbidden)
// ---------------------------------------------------------------------------
__device__ __half g_qh[BB * SS * DD];
__device__ __half g_ql[BB * SS * DD];
__device__ __half g_kh[BB * SS * DD];
__device__ __half g_kl[BB * SS * DD];
__device__ __half g_vth[BB * DD * SS];   // v transposed [b][d][s]
__device__ __half g_vtl[BB * DD * SS];
__device__ float  g_sc[(size_t)BB * SS * SS];   // raw scores
__device__ __half g_ph[(size_t)BB * SS * SS];   // softmax hi
__device__ __half g_pl[(size_t)BB * SS * SS];   // softmax lo

// ---------------------------------------------------------------------------
// Small PTX helpers (all baseline ISA; no sm_103a-only features)
// ---------------------------------------------------------------------------
__device__ __forceinline__ uint32_t smem_u32(const void* p) {
    uint32_t a;
    asm("{ .reg .u64 t; cvta.to.shared.u64 t, %1; cvt.u32.u64 %0, t; }"
        : "=r"(a) : "l"(p));
    return a;
}

__device__ __forceinline__ void cp_async16(uint32_t dst, const void* src) {
    asm volatile("cp.async.cg.shared.global [%0], [%1], 16;"
                 :: "r"(dst), "l"(src) : "memory");
}
__device__ __forceinline__ void cp_commit() {
    asm volatile("cp.async.commit_group;" ::: "memory");
}
template <int N>
__device__ __forceinline__ void cp_wait() {
    asm volatile("cp.async.wait_group %0;" :: "n"(N) : "memory");
}

__device__ __forceinline__ void ldsm_x4(uint32_t& r0, uint32_t& r1,
                                        uint32_t& r2, uint32_t& r3, uint32_t addr) {
    asm volatile("ldmatrix.sync.aligned.m8n8.x4.shared.b16 {%0,%1,%2,%3}, [%4];"
                 : "=r"(r0), "=r"(r1), "=r"(r2), "=r"(r3) : "r"(addr));
}

__device__ __forceinline__ void mma16816(float* c, const uint32_t* a, const uint32_t* b) {
    asm volatile(
        "mma.sync.aligned.m16n8k16.row.col.f32.f16.f16.f32 "
        "{%0,%1,%2,%3}, {%4,%5,%6,%7}, {%8,%9}, {%0,%1,%2,%3};"
        : "+f"(c[0]), "+f"(c[1]), "+f"(c[2]), "+f"(c[3])
        : "r"(a[0]), "r"(a[1]), "r"(a[2]), "r"(a[3]), "r"(b[0]), "r"(b[1]));
}

// ---------------------------------------------------------------------------
// Kernel 1: Givens-rotate Q into q,k (fp16 hi/lo split), layout [S, D]
// ---------------------------------------------------------------------------
__global__ void prep_kernel(const float* __restrict__ Q,
                            const float* __restrict__ rot_w) {
    int idx = blockIdx.x * blockDim.x + threadIdx.x;
    int total = BB * SS * (DD / 2);
    if (idx >= total) return;
    int p = idx % (DD / 2);
    size_t base = (size_t)(idx / (DD / 2)) * DD;
    float2 x = *(const float2*)(Q + base + 2 * p);
#pragma unroll
    for (int r = 0; r < 2; r++) {
        float c = rot_w[r * DD + 2 * p];
        float s = rot_w[r * DD + 2 * p + 1];
        float inv = rsqrtf(c * c + s * s);
        c *= inv; s *= inv;
        float y0 = c * x.x - s * x.y;
        float y1 = c * x.y + s * x.x;
        __half h0 = __float2half(y0), h1 = __float2half(y1);
        __half l0 = __float2half(y0 - __half2float(h0));
        __half l1 = __float2half(y1 - __half2float(h1));
        *(__half2*)((r == 0 ? g_qh : g_kh) + base + 2 * p) = __halves2half2(h0, h1);
        *(__half2*)((r == 0 ? g_ql : g_kl) + base + 2 * p) = __halves2half2(l0, l1);
    }
}

// ---------------------------------------------------------------------------
// Kernel 2: rotate v and write TRANSPOSED [b][d][s] fp16 hi/lo
// ---------------------------------------------------------------------------
__global__ __launch_bounds__(256) void vrot_kernel(const float* __restrict__ Q,
                                                   const float* __restrict__ rot_w) {
    __shared__ __half th[64][33];
    __shared__ __half tl[64][33];
    int d0 = blockIdx.x * 64, s0 = blockIdx.y * 32, b = blockIdx.z;
    int tx = threadIdx.x, ty = threadIdx.y;
    int p = d0 / 2 + tx;
    float c = rot_w[2 * DD + 2 * p];
    float s = rot_w[2 * DD + 2 * p + 1];
    float inv = rsqrtf(c * c + s * s);
    c *= inv; s *= inv;
#pragma unroll
    for (int r = 0; r < 4; r++) {
        int srow = s0 + ty + 8 * r;
        float2 x = *(const float2*)(Q + ((size_t)b * SS + srow) * DD + d0 + 2 * tx);
        float y0 = c * x.x - s * x.y;
        float y1 = c * x.y + s * x.x;
        __half h0 = __float2half(y0), h1 = __float2half(y1);
        th[2 * tx][ty + 8 * r] = h0;
        tl[2 * tx][ty + 8 * r] = __float2half(y0 - __half2float(h0));
        th[2 * tx + 1][ty + 8 * r] = h1;
        tl[2 * tx + 1][ty + 8 * r] = __float2half(y1 - __half2float(h1));
    }
    __syncthreads();
#pragma unroll
    for (int r = 0; r < 8; r++) {
        int d = r * 8 + ty;
        size_t o = ((size_t)b * DD + d0 + d) * SS + s0 + tx;
        g_vth[o] = th[d][tx];
        g_vtl[o] = tl[d][tx];
    }
}

// ---------------------------------------------------------------------------
// mma.sync NT GEMM:  C[M,N] += sum over 3 phases of A_ph[M,K] * B_ph[N,K]^T
// CTA tile 128x128, 8 warps (2x4) each 64x32, K-chunk 32, double-buffered.
// ---------------------------------------------------------------------------
#define CHUNK 32
#define PAD 40   // smem row stride in halves (80B: conflict-free ldmatrix)

__device__ __forceinline__ void load_tile(const __half* gA, const __half* gB,
                                          int lda, int ldb,
                                          uint32_t sA, uint32_t sB, int tid) {
    // 128 rows x 4 granules(16B) each for A and B
#pragma unroll
    for (int i = 0; i < 2; i++) {
        int lin = tid + i * 256;      // 0..511
        int row = lin >> 2;
        int g = lin & 3;
        cp_async16(sA + (row * PAD + g * 8) * 2, gA + (size_t)row * lda + g * 8);
    }
#pragma unroll
    for (int i = 0; i < 2; i++) {
        int lin = tid + i * 256;
        int row = lin >> 2;
        int g = lin & 3;
        cp_async16(sB + (row * PAD + g * 8) * 2, gB + (size_t)row * ldb + g * 8);
    }
}

__device__ __forceinline__ void gemm_mma_body(
    const __half* A0, const __half* A1, const __half* A2,
    const __half* B0, const __half* B1, const __half* B2,
    int K, int lda, int ldb,
    size_t strideA, size_t strideB, size_t strideC,
    float* __restrict__ C, int ldc) {
    __shared__ __half shA[2][128 * PAD];
    __shared__ __half shB[2][128 * PAD];

    int tid = threadIdx.x;
    int wid = tid >> 5, lid = tid & 31;
    int wm = wid & 1, wn = wid >> 1;
    int b = blockIdx.z;
    int m0 = blockIdx.y * 128, n0 = blockIdx.x * 128;

    const __half* Aph[3] = {A0 + b * strideA, A1 + b * strideA, A2 + b * strideA};
    const __half* Bph[3] = {B0 + b * strideB, B1 + b * strideB, B2 + b * strideB};
    int kiters = K / CHUNK;
    int niter = 3 * kiters;

    uint32_t sAu[2] = {smem_u32(shA[0]), smem_u32(shA[1])};
    uint32_t sBu[2] = {smem_u32(shB[0]), smem_u32(shB[1])};

    // per-lane ldmatrix base offsets (bytes)
    uint32_t offA[4], offB[2];
#pragma unroll
    for (int am = 0; am < 4; am++)
        offA[am] = ((wm * 64 + am * 16 + (lid & 15)) * PAD + (lid >> 4) * 8) * 2;
#pragma unroll
    for (int bq = 0; bq < 2; bq++)
        offB[bq] = ((wn * 32 + bq * 16 + (lid & 7) + ((lid >> 4) << 3)) * PAD +
                    ((lid >> 3) & 1) * 8) * 2;

    float acc[4][4][4];
#pragma unroll
    for (int i = 0; i < 4; i++)
#pragma unroll
        for (int j = 0; j < 4; j++)
#pragma unroll
            for (int q = 0; q < 4; q++) acc[i][j][q] = 0.0f;

    // prologue
    {
        const __half* ga = Aph[0] + (size_t)m0 * lda;
        const __half* gb = Bph[0] + (size_t)n0 * ldb;
        load_tile(ga, gb, lda, ldb, sAu[0], sBu[0], tid);
        cp_commit();
    }

    for (int it = 0; it < niter; it++) {
        int cur = it & 1;
        if (it + 1 < niter) {
            int ph = (it + 1) / kiters;
            int kb = ((it + 1) % kiters) * CHUNK;
            const __half* ga = Aph[ph] + (size_t)m0 * lda + kb;
            const __half* gb = Bph[ph] + (size_t)n0 * ldb + kb;
            load_tile(ga, gb, lda, ldb, sAu[cur ^ 1], sBu[cur ^ 1], tid);
            cp_commit();
            cp_wait<1>();
        } else {
            cp_wait<0>();
        }
        __syncthreads();

#pragma unroll
        for (int ks = 0; ks < 2; ks++) {
            int kk = ks * 16;
            uint32_t a[4][4], bf[4][2];
#pragma unroll
            for (int am = 0; am < 4; am++)
                ldsm_x4(a[am][0], a[am][1], a[am][2], a[am][3],
                        sAu[cur] + offA[am] + kk * 2);
#pragma unroll
            for (int bq = 0; bq < 2; bq++) {
                uint32_t r0, r1, r2, r3;
                ldsm_x4(r0, r1, r2, r3, sBu[cur] + offB[bq] + kk * 2);
                bf[bq * 2][0] = r0; bf[bq * 2][1] = r1;
                bf[bq * 2 + 1][0] = r2; bf[bq * 2 + 1][1] = r3;
            }
#pragma unroll
            for (int am = 0; am < 4; am++)
#pragma unroll
                for (int bn = 0; bn < 4; bn++)
                    mma16816(acc[am][bn], a[am], bf[bn]);
        }
        __syncthreads();
    }

    // epilogue
#pragma unroll
    for (int am = 0; am < 4; am++) {
        int row = m0 + wm * 64 + am * 16 + (lid >> 2);
#pragma unroll
        for (int bn = 0; bn < 4; bn++) {
            int col = n0 + wn * 32 + bn * 8 + (lid & 3) * 2;
            float* p0 = C + b * strideC + (size_t)row * ldc + col;
            float* p1 = C + b * strideC + (size_t)(row + 8) * ldc + col;
            *(float2*)p0 = make_float2(acc[am][bn][0], acc[am][bn][1]);
            *(float2*)p1 = make_float2(acc[am][bn][2], acc[am][bn][3]);
        }
    }
}

__global__ __launch_bounds__(256) void gemm_qk_kernel() {
    // scores = q.k^T : qh.kh + ql.kh + qh.kl
    gemm_mma_body(g_qh, g_ql, g_qh, g_kh, g_kh, g_kl,
                  DD, DD, DD,
                  (size_t)SS * DD, (size_t)SS * DD, (size_t)SS * SS,
                  g_sc, SS);
}

__global__ __launch_bounds__(256) void gemm_pv_kernel(float* __restrict__ out) {
    // out = P.v : ph.vh + pl.vh + ph.vl   (B = v^T [D,S])
    gemm_mma_body(g_ph, g_pl, g_ph, g_vth, g_vth, g_vtl,
                  SS, SS, SS,
                  (size_t)SS * SS, (size_t)DD * SS, (size_t)SS * DD,
                  out, DD);
}

// ---------------------------------------------------------------------------
// Softmax((2+2x)/scale + bias) == softmax(2x/scale) (shift-invariant).
// Writes fp16 hi/lo split of probabilities. One block per row.
// ---------------------------------------------------------------------------
__global__ __launch_bounds__(256) void softmax_kernel(const float* __restrict__ scale) {
    size_t rowoff = (size_t)blockIdx.x * SS;
    const float* row = g_sc + rowoff;
    float alpha = 2.0f / scale[0];
    int tid = threadIdx.x;

    float vals[8];
    float lmax = -FLT_MAX;
#pragma unroll
    for (int i = 0; i < 8; i++) {
        float t = row[tid + i * 256] * alpha;
        vals[i] = t;
        lmax = fmaxf(lmax, t);
    }
    __shared__ float sred[8];
    __shared__ float sbc;
    float v = lmax;
#pragma unroll
    for (int o = 16; o > 0; o >>= 1) v = fmaxf(v, __shfl_xor_sync(0xffffffffu, v, o));
    if ((tid & 31) == 0) sred[tid >> 5] = v;
    __syncthreads();
    if (tid == 0) {
        float m = sred[0];
#pragma unroll
        for (int i = 1; i < 8; i++) m = fmaxf(m, sred[i]);
        sbc = m;
    }
    __syncthreads();
    float m = sbc;
    float lsum = 0.0f;
#pragma unroll
    for (int i = 0; i < 8; i++) {
        vals[i] = __expf(vals[i] - m);
        lsum += vals[i];
    }
    v = lsum;
#pragma unroll
    for (int o = 16; o > 0; o >>= 1) v += __shfl_xor_sync(0xffffffffu, v, o);
    __syncthreads();
    if ((tid & 31) == 0) sred[tid >> 5] = v;
    __syncthreads();
    if (tid == 0) {
        float t = 0.0f;
#pragma unroll
        for (int i = 0; i < 8; i++) t += sred[i];
        sbc = 1.0f / t;
    }
    __syncthreads();
    float inv = sbc;
#pragma unroll
    for (int i = 0; i < 8; i++) {
        float p = vals[i] * inv;
        __half h = __float2half(p);
        __half l = __float2half(p - __half2float(h));
        g_ph[rowoff + tid + i * 256] = h;
        g_pl[rowoff + tid + i * 256] = l;
    }
}

// ---------------------------------------------------------------------------
// Row L2 normalization of out rows (D=1024)
// ---------------------------------------------------------------------------
__global__ __launch_bounds__(256) void normalize_kernel(float* __restrict__ out) {
    float* row = out + (size_t)blockIdx.x * DD;
    int tid = threadIdx.x;
    float v[4];
    float ss = 0.0f;
#pragma unroll
    for (int i = 0; i < 4; i++) {
        v[i] = row[tid + i * 256];
        ss = fmaf(v[i], v[i], ss);
    }
    __shared__ float sred[8];
    __shared__ float sbc;
    float r = ss;
#pragma unroll
    for (int o = 16; o > 0; o >>= 1) r += __shfl_xor_sync(0xffffffffu, r, o);
    if ((tid & 31) == 0) sred[tid >> 5] = r;
    __syncthreads();
    if (tid == 0) {
        float t = 0.0f;
#pragma unroll
        for (int i = 0; i < 8; i++) t += sred[i];
        sbc = rsqrtf(fmaxf(fabsf(t), 1e-8f));
    }
    __syncthreads();
    float inv = sbc;
#pragma unroll
    for (int i = 0; i < 4; i++) row[tid + i * 256] = v[i] * inv;
}

// ---------------------------------------------------------------------------
extern "C" void kernel_launch(void* const* d_in, const int* in_sizes, int n_in,
                              void* d_out, int out_size) {
    (void)in_sizes; (void)n_in; (void)out_size;
    const float* Q     = (const float*)d_in[0];
    const float* rot_w = (const float*)d_in[1];
    const float* scale = (const float*)d_in[2];
    float* out = (float*)d_out;

    int pairs = BB * SS * (DD / 2);
    prep_kernel<<<(pairs + 255) / 256, 256>>>(Q, rot_w);
    vrot_kernel<<<dim3(DD / 64, SS / 32, BB), dim3(32, 8)>>>(Q, rot_w);

    gemm_qk_kernel<<<dim3(SS / 128, SS / 128, BB), 256>>>();
    softmax_kernel<<<BB * SS, 256>>>(scale);
    gemm_pv_kernel<<<dim3(DD / 128, SS / 128, BB), 256>>>(out);
    normalize_kernel<<<BB * SS, 256>>>(out);
}

// round 4
// speedup vs baseline: 2.7670x; 1.6704x over previous
#include <cuda_runtime.h>
#include <cuda_fp16.h>
#include <math.h>
#include <float.h>
#include <stdint.h>

#define BB 4
#define SS 2048
#define DD 1024

// ---------------------------------------------------------------------------
// Scratch (static device globals; runtime allocation is forbidden)
// ---------------------------------------------------------------------------
__device__ __half g_qh[BB * SS * DD];
__device__ __half g_ql[BB * SS * DD];
__device__ __half g_kh[BB * SS * DD];
__device__ __half g_kl[BB * SS * DD];
__device__ __half g_vth[BB * DD * SS];   // v transposed [b][d][s]
__device__ __half g_vtl[BB * DD * SS];
__device__ float  g_sc[(size_t)BB * SS * SS];   // raw scores
__device__ __half g_ph[(size_t)BB * SS * SS];   // softmax hi
__device__ __half g_pl[(size_t)BB * SS * SS];   // softmax lo

// ---------------------------------------------------------------------------
// PTX helpers (baseline ISA only — compute_103 safe)
// ---------------------------------------------------------------------------
__device__ __forceinline__ uint32_t smem_u32(const void* p) {
    uint32_t a;
    asm("{ .reg .u64 t; cvta.to.shared.u64 t, %1; cvt.u32.u64 %0, t; }"
        : "=r"(a) : "l"(p));
    return a;
}
__device__ __forceinline__ void cp_async16(uint32_t dst, const void* src) {
    asm volatile("cp.async.cg.shared.global [%0], [%1], 16;"
                 :: "r"(dst), "l"(src) : "memory");
}
__device__ __forceinline__ void cp_commit() {
    asm volatile("cp.async.commit_group;" ::: "memory");
}
template <int N>
__device__ __forceinline__ void cp_wait() {
    asm volatile("cp.async.wait_group %0;" :: "n"(N) : "memory");
}
__device__ __forceinline__ void ldsm_x4(uint32_t& r0, uint32_t& r1,
                                        uint32_t& r2, uint32_t& r3, uint32_t addr) {
    asm volatile("ldmatrix.sync.aligned.m8n8.x4.shared.b16 {%0,%1,%2,%3}, [%4];"
                 : "=r"(r0), "=r"(r1), "=r"(r2), "=r"(r3) : "r"(addr));
}
__device__ __forceinline__ void mma16816(float* c, const uint32_t* a, const uint32_t* b) {
    asm volatile(
        "mma.sync.aligned.m16n8k16.row.col.f32.f16.f16.f32 "
        "{%0,%1,%2,%3}, {%4,%5,%6,%7}, {%8,%9}, {%0,%1,%2,%3};"
        : "+f"(c[0]), "+f"(c[1]), "+f"(c[2]), "+f"(c[3])
        : "r"(a[0]), "r"(a[1]), "r"(a[2]), "r"(a[3]), "r"(b[0]), "r"(b[1]));
}

// ---------------------------------------------------------------------------
// Kernel 1: Givens-rotate Q into q,k (fp16 hi/lo split), layout [S, D]
// ---------------------------------------------------------------------------
__global__ void prep_kernel(const float* __restrict__ Q,
                            const float* __restrict__ rot_w) {
    int idx = blockIdx.x * blockDim.x + threadIdx.x;
    int total = BB * SS * (DD / 2);
    if (idx >= total) return;
    int p = idx % (DD / 2);
    size_t base = (size_t)(idx / (DD / 2)) * DD;
    float2 x = *(const float2*)(Q + base + 2 * p);
#pragma unroll
    for (int r = 0; r < 2; r++) {
        float c = rot_w[r * DD + 2 * p];
        float s = rot_w[r * DD + 2 * p + 1];
        float inv = rsqrtf(c * c + s * s);
        c *= inv; s *= inv;
        float y0 = c * x.x - s * x.y;
        float y1 = c * x.y + s * x.x;
        __half h0 = __float2half(y0), h1 = __float2half(y1);
        __half l0 = __float2half(y0 - __half2float(h0));
        __half l1 = __float2half(y1 - __half2float(h1));
        *(__half2*)((r == 0 ? g_qh : g_kh) + base + 2 * p) = __halves2half2(h0, h1);
        *(__half2*)((r == 0 ? g_ql : g_kl) + base + 2 * p) = __halves2half2(l0, l1);
    }
}

// ---------------------------------------------------------------------------
// Kernel 2: rotate v and write TRANSPOSED [b][d][s] fp16 hi/lo
// ---------------------------------------------------------------------------
__global__ __launch_bounds__(256) void vrot_kernel(const float* __restrict__ Q,
                                                   const float* __restrict__ rot_w) {
    __shared__ __half th[64][33];
    __shared__ __half tl[64][33];
    int d0 = blockIdx.x * 64, s0 = blockIdx.y * 32, b = blockIdx.z;
    int tx = threadIdx.x, ty = threadIdx.y;
    int p = d0 / 2 + tx;
    float c = rot_w[2 * DD + 2 * p];
    float s = rot_w[2 * DD + 2 * p + 1];
    float inv = rsqrtf(c * c + s * s);
    c *= inv; s *= inv;
#pragma unroll
    for (int r = 0; r < 4; r++) {
        int srow = s0 + ty + 8 * r;
        float2 x = *(const float2*)(Q + ((size_t)b * SS + srow) * DD + d0 + 2 * tx);
        float y0 = c * x.x - s * x.y;
        float y1 = c * x.y + s * x.x;
        __half h0 = __float2half(y0), h1 = __float2half(y1);
        th[2 * tx][ty + 8 * r] = h0;
        tl[2 * tx][ty + 8 * r] = __float2half(y0 - __half2float(h0));
        th[2 * tx + 1][ty + 8 * r] = h1;
        tl[2 * tx + 1][ty + 8 * r] = __float2half(y1 - __half2float(h1));
    }
    __syncthreads();
#pragma unroll
    for (int r = 0; r < 8; r++) {
        int d = r * 8 + ty;
        size_t o = ((size_t)b * DD + d0 + d) * SS + s0 + tx;
        g_vth[o] = th[d][tx];
        g_vtl[o] = tl[d][tx];
    }
}

// ---------------------------------------------------------------------------
// Fused split-fp16 NT GEMM:
//   C[M,N] = Ah.Bh^T + Al.Bh^T + Ah.Bl^T
// CTA tile 128x256, 8 warps (2m x 4n) of 64x64, K-chunk 32, double-buffered.
// Dynamic smem layout per buffer (halves, PAD=40 per 32-k row):
//   Ah @ 0, Al @ 5120, Bh @ 10240, Bl @ 20480 ; buffer stride 30720
// ---------------------------------------------------------------------------
#define CHUNK 32
#define PAD 40
#define BUF_HALVES 30720
#define SMEM_BYTES (2 * BUF_HALVES * 2)

__device__ __forceinline__ void load_tile_fused(
    const __half* gAh, const __half* gAl,
    const __half* gBh, const __half* gBl,
    int lda, int ldb, int kb, uint32_t s0, int tid) {
#pragma unroll
    for (int i = 0; i < 2; i++) {
        int lin = tid + i * 256;          // 0..511 : A rows 0..127 x 4 granules
        int row = lin >> 2;
        int g = lin & 3;
        uint32_t d = (uint32_t)(row * PAD + g * 8) * 2;
        const __half* pa = gAh + (size_t)row * lda + kb + g * 8;
        const __half* pl = gAl + (size_t)row * lda + kb + g * 8;
        cp_async16(s0 + d, pa);
        cp_async16(s0 + 10240 + d, pl);
    }
#pragma unroll
    for (int i = 0; i < 4; i++) {
        int lin = tid + i * 256;          // 0..1023 : B rows 0..255 x 4 granules
        int row = lin >> 2;
        int g = lin & 3;
        uint32_t d = (uint32_t)(row * PAD + g * 8) * 2;
        const __half* pb = gBh + (size_t)row * ldb + kb + g * 8;
        const __half* pl = gBl + (size_t)row * ldb + kb + g * 8;
        cp_async16(s0 + 20480 + d, pb);
        cp_async16(s0 + 40960 + d, pl);
    }
}

__device__ __forceinline__ void gemm_fused_body(
    const __half* Ah, const __half* Al,
    const __half* Bh, const __half* Bl,
    int K, int lda, int ldb,
    size_t strideA, size_t strideB, size_t strideC,
    float* __restrict__ C, int ldc) {
    extern __shared__ __half sm[];
    uint32_t sbase = smem_u32(sm);

    int tid = threadIdx.x;
    int wid = tid >> 5, lid = tid & 31;
    int wm = wid & 1;      // 0..1  -> 64 rows each
    int wn = wid >> 1;     // 0..3  -> 64 cols each
    int b = blockIdx.z;
    int m0 = blockIdx.y * 128, n0 = blockIdx.x * 256;

    const __half* gAh = Ah + b * strideA + (size_t)m0 * lda;
    const __half* gAl = Al + b * strideA + (size_t)m0 * lda;
    const __half* gBh = Bh + b * strideB + (size_t)n0 * ldb;
    const __half* gBl = Bl + b * strideB + (size_t)n0 * ldb;

    uint32_t offA[4], offB[4];
#pragma unroll
    for (int am = 0; am < 4; am++)
        offA[am] = ((wm * 64 + am * 16 + (lid & 15)) * PAD + (lid >> 4) * 8) * 2;
#pragma unroll
    for (int bq = 0; bq < 4; bq++)
        offB[bq] = ((wn * 64 + bq * 16 + (lid & 7) + ((lid >> 4) << 3)) * PAD +
                    ((lid >> 3) & 1) * 8) * 2;

    float acc[4][8][4];
#pragma unroll
    for (int i = 0; i < 4; i++)
#pragma unroll
        for (int j = 0; j < 8; j++)
#pragma unroll
            for (int q = 0; q < 4; q++) acc[i][j][q] = 0.0f;

    int niter = K / CHUNK;
    load_tile_fused(gAh, gAl, gBh, gBl, lda, ldb, 0, sbase, tid);
    cp_commit();

    for (int it = 0; it < niter; it++) {
        int cur = it & 1;
        if (it + 1 < niter) {
            load_tile_fused(gAh, gAl, gBh, gBl, lda, ldb, (it + 1) * CHUNK,
                            sbase + (cur ^ 1) * (BUF_HALVES * 2), tid);
            cp_commit();
            cp_wait<1>();
        } else {
            cp_wait<0>();
        }
        __syncthreads();

        uint32_t sA = sbase + cur * (BUF_HALVES * 2);
        uint32_t sAl_ = sA + 10240;
        uint32_t sBh_ = sA + 20480;
        uint32_t sBl_ = sA + 40960;

#pragma unroll
        for (int ks = 0; ks < 2; ks++) {
            uint32_t koff = ks * 32;   // 16 halves = 32 bytes
            uint32_t a[4][4], bh[8][2], bl[8][2];
            // A-hi and B-hi fragments
#pragma unroll
            for (int am = 0; am < 4; am++)
                ldsm_x4(a[am][0], a[am][1], a[am][2], a[am][3],
                        sA + offA[am] + koff);
#pragma unroll
            for (int bq = 0; bq < 4; bq++) {
                uint32_t r0, r1, r2, r3;
                ldsm_x4(r0, r1, r2, r3, sBh_ + offB[bq] + koff);
                bh[bq * 2][0] = r0; bh[bq * 2][1] = r1;
                bh[bq * 2 + 1][0] = r2; bh[bq * 2 + 1][1] = r3;
            }
            // term 1: Ah * Bh
#pragma unroll
            for (int am = 0; am < 4; am++)
#pragma unroll
                for (int bn = 0; bn < 8; bn++)
                    mma16816(acc[am][bn], a[am], bh[bn]);
            // term 2: Ah * Bl
#pragma unroll
            for (int bq = 0; bq < 4; bq++) {
                uint32_t r0, r1, r2, r3;
                ldsm_x4(r0, r1, r2, r3, sBl_ + offB[bq] + koff);
                bl[bq * 2][0] = r0; bl[bq * 2][1] = r1;
                bl[bq * 2 + 1][0] = r2; bl[bq * 2 + 1][1] = r3;
            }
#pragma unroll
            for (int am = 0; am < 4; am++)
#pragma unroll
                for (int bn = 0; bn < 8; bn++)
                    mma16816(acc[am][bn], a[am], bl[bn]);
            // term 3: Al * Bh (overwrite A frags with lo)
#pragma unroll
            for (int am = 0; am < 4; am++)
                ldsm_x4(a[am][0], a[am][1], a[am][2], a[am][3],
                        sAl_ + offA[am] + koff);
#pragma unroll
            for (int am = 0; am < 4; am++)
#pragma unroll
                for (int bn = 0; bn < 8; bn++)
                    mma16816(acc[am][bn], a[am], bh[bn]);
        }
        __syncthreads();
    }

    // epilogue
#pragma unroll
    for (int am = 0; am < 4; am++) {
        int row = m0 + wm * 64 + am * 16 + (lid >> 2);
#pragma unroll
        for (int bn = 0; bn < 8; bn++) {
            int col = n0 + wn * 64 + bn * 8 + (lid & 3) * 2;
            float* p0 = C + b * strideC + (size_t)row * ldc + col;
            float* p1 = C + b * strideC + (size_t)(row + 8) * ldc + col;
            *(float2*)p0 = make_float2(acc[am][bn][0], acc[am][bn][1]);
            *(float2*)p1 = make_float2(acc[am][bn][2], acc[am][bn][3]);
        }
    }
}

__global__ __launch_bounds__(256) void gemm_qk_kernel() {
    // scores = qh.kh + ql.kh + qh.kl
    gemm_fused_body(g_qh, g_ql, g_kh, g_kl,
                    DD, DD, DD,
                    (size_t)SS * DD, (size_t)SS * DD, (size_t)SS * SS,
                    g_sc, SS);
}

__global__ __launch_bounds__(256) void gemm_pv_kernel(float* __restrict__ out) {
    // out = ph.vh + pl.vh + ph.vl   (B = v^T [D,S])
    gemm_fused_body(g_ph, g_pl, g_vth, g_vtl,
                    SS, SS, SS,
                    (size_t)SS * SS, (size_t)DD * SS, (size_t)SS * DD,
                    out, DD);
}

// ---------------------------------------------------------------------------
// Softmax((2+2x)/scale + bias) == softmax(2x/scale) (shift-invariant).
// Writes fp16 hi/lo split of probabilities. One block per row.
// ---------------------------------------------------------------------------
__global__ __launch_bounds__(256) void softmax_kernel(const float* __restrict__ scale) {
    size_t rowoff = (size_t)blockIdx.x * SS;
    const float* row = g_sc + rowoff;
    float alpha = 2.0f / scale[0];
    int tid = threadIdx.x;

    float vals[8];
    float lmax = -FLT_MAX;
#pragma unroll
    for (int i = 0; i < 8; i++) {
        float t = row[tid + i * 256] * alpha;
        vals[i] = t;
        lmax = fmaxf(lmax, t);
    }
    __shared__ float sred[8];
    __shared__ float sbc;
    float v = lmax;
#pragma unroll
    for (int o = 16; o > 0; o >>= 1) v = fmaxf(v, __shfl_xor_sync(0xffffffffu, v, o));
    if ((tid & 31) == 0) sred[tid >> 5] = v;
    __syncthreads();
    if (tid == 0) {
        float m = sred[0];
#pragma unroll
        for (int i = 1; i < 8; i++) m = fmaxf(m, sred[i]);
        sbc = m;
    }
    __syncthreads();
    float m = sbc;
    float lsum = 0.0f;
#pragma unroll
    for (int i = 0; i < 8; i++) {
        vals[i] = __expf(vals[i] - m);
        lsum += vals[i];
    }
    v = lsum;
#pragma unroll
    for (int o = 16; o > 0; o >>= 1) v += __shfl_xor_sync(0xffffffffu, v, o);
    __syncthreads();
    if ((tid & 31) == 0) sred[tid >> 5] = v;
    __syncthreads();
    if (tid == 0) {
        float t = 0.0f;
#pragma unroll
        for (int i = 0; i < 8; i++) t += sred[i];
        sbc = 1.0f / t;
    }
    __syncthreads();
    float inv = sbc;
#pragma unroll
    for (int i = 0; i < 8; i++) {
        float p = vals[i] * inv;
        __half h = __float2half(p);
        __half l = __float2half(p - __half2float(h));
        g_ph[rowoff + tid + i * 256] = h;
        g_pl[rowoff + tid + i * 256] = l;
    }
}

// ---------------------------------------------------------------------------
// Row L2 normalization of out rows (D=1024)
// ---------------------------------------------------------------------------
__global__ __launch_bounds__(256) void normalize_kernel(float* __restrict__ out) {
    float* row = out + (size_t)blockIdx.x * DD;
    int tid = threadIdx.x;
    float v[4];
    float ss = 0.0f;
#pragma unroll
    for (int i = 0; i < 4; i++) {
        v[i] = row[tid + i * 256];
        ss = fmaf(v[i], v[i], ss);
    }
    __shared__ float sred[8];
    __shared__ float sbc;
    float r = ss;
#pragma unroll
    for (int o = 16; o > 0; o >>= 1) r += __shfl_xor_sync(0xffffffffu, r, o);
    if ((tid & 31) == 0) sred[tid >> 5] = r;
    __syncthreads();
    if (tid == 0) {
        float t = 0.0f;
#pragma unroll
        for (int i = 0; i < 8; i++) t += sred[i];
        sbc = rsqrtf(fmaxf(fabsf(t), 1e-8f));
    }
    __syncthreads();
    float inv = sbc;
#pragma unroll
    for (int i = 0; i < 4; i++) row[tid + i * 256] = v[i] * inv;
}

// ---------------------------------------------------------------------------
extern "C" void kernel_launch(void* const* d_in, const int* in_sizes, int n_in,
                              void* d_out, int out_size) {
    (void)in_sizes; (void)n_in; (void)out_size;
    const float* Q     = (const float*)d_in[0];
    const float* rot_w = (const float*)d_in[1];
    const float* scale = (const float*)d_in[2];
    float* out = (float*)d_out;

    cudaFuncSetAttribute(gemm_qk_kernel,
                         cudaFuncAttributeMaxDynamicSharedMemorySize, SMEM_BYTES);
    cudaFuncSetAttribute(gemm_pv_kernel,
                         cudaFuncAttributeMaxDynamicSharedMemorySize, SMEM_BYTES);

    int pairs = BB * SS * (DD / 2);
    prep_kernel<<<(pairs + 255) / 256, 256>>>(Q, rot_w);
    vrot_kernel<<<dim3(DD / 64, SS / 32, BB), dim3(32, 8)>>>(Q, rot_w);

    gemm_qk_kernel<<<dim3(SS / 256, SS / 128, BB), 256, SMEM_BYTES>>>();
    softmax_kernel<<<BB * SS, 256>>>(scale);
    gemm_pv_kernel<<<dim3(DD / 256, SS / 128, BB), 256, SMEM_BYTES>>>(out);
    normalize_kernel<<<BB * SS, 256>>>(out);
}

// round 5
// speedup vs baseline: 3.2016x; 1.1571x over previous
#include <cuda_runtime.h>
#include <cuda_fp16.h>
#include <math.h>
#include <float.h>
#include <stdint.h>

#define BB 4
#define SS 2048
#define DD 1024

// ---------------------------------------------------------------------------
// Scratch (static device globals; runtime allocation is forbidden)
// ---------------------------------------------------------------------------
__device__ __half g_qh[BB * SS * DD];
__device__ __half g_ql[BB * SS * DD];
__device__ __half g_kh[BB * SS * DD];
__device__ __half g_kl[BB * SS * DD];
__device__ __half g_vth[BB * DD * SS];   // v transposed [b][d][s], hi only
__device__ float  g_sc[(size_t)BB * SS * SS];   // raw scores
__device__ __half g_ph[(size_t)BB * SS * SS];   // softmax hi
__device__ __half g_pl[(size_t)BB * SS * SS];   // softmax lo

// ---------------------------------------------------------------------------
// PTX helpers (baseline ISA only — compute_103 safe)
// ---------------------------------------------------------------------------
__device__ __forceinline__ uint32_t smem_u32(const void* p) {
    uint32_t a;
    asm("{ .reg .u64 t; cvta.to.shared.u64 t, %1; cvt.u32.u64 %0, t; }"
        : "=r"(a) : "l"(p));
    return a;
}
__device__ __forceinline__ void cp_async16(uint32_t dst, const void* src) {
    asm volatile("cp.async.cg.shared.global [%0], [%1], 16;"
                 :: "r"(dst), "l"(src) : "memory");
}
__device__ __forceinline__ void cp_commit() {
    asm volatile("cp.async.commit_group;" ::: "memory");
}
template <int N>
__device__ __forceinline__ void cp_wait() {
    asm volatile("cp.async.wait_group %0;" :: "n"(N) : "memory");
}
__device__ __forceinline__ void ldsm_x4(uint32_t& r0, uint32_t& r1,
                                        uint32_t& r2, uint32_t& r3, uint32_t addr) {
    asm volatile("ldmatrix.sync.aligned.m8n8.x4.shared.b16 {%0,%1,%2,%3}, [%4];"
                 : "=r"(r0), "=r"(r1), "=r"(r2), "=r"(r3) : "r"(addr));
}
__device__ __forceinline__ void mma16816(float* c, const uint32_t* a, const uint32_t* b) {
    asm volatile(
        "mma.sync.aligned.m16n8k16.row.col.f32.f16.f16.f32 "
        "{%0,%1,%2,%3}, {%4,%5,%6,%7}, {%8,%9}, {%0,%1,%2,%3};"
        : "+f"(c[0]), "+f"(c[1]), "+f"(c[2]), "+f"(c[3])
        : "r"(a[0]), "r"(a[1]), "r"(a[2]), "r"(a[3]), "r"(b[0]), "r"(b[1]));
}

// ---------------------------------------------------------------------------
// Kernel 1: Givens-rotate Q into q,k (fp16 hi/lo split), layout [S, D]
// ---------------------------------------------------------------------------
__global__ void prep_kernel(const float* __restrict__ Q,
                            const float* __restrict__ rot_w) {
    int idx = blockIdx.x * blockDim.x + threadIdx.x;
    int total = BB * SS * (DD / 2);
    if (idx >= total) return;
    int p = idx % (DD / 2);
    size_t base = (size_t)(idx / (DD / 2)) * DD;
    float2 x = *(const float2*)(Q + base + 2 * p);
#pragma unroll
    for (int r = 0; r < 2; r++) {
        float c = rot_w[r * DD + 2 * p];
        float s = rot_w[r * DD + 2 * p + 1];
        float inv = rsqrtf(c * c + s * s);
        c *= inv; s *= inv;
        float y0 = c * x.x - s * x.y;
        float y1 = c * x.y + s * x.x;
        __half h0 = __float2half(y0), h1 = __float2half(y1);
        __half l0 = __float2half(y0 - __half2float(h0));
        __half l1 = __float2half(y1 - __half2float(h1));
        *(__half2*)((r == 0 ? g_qh : g_kh) + base + 2 * p) = __halves2half2(h0, h1);
        *(__half2*)((r == 0 ? g_ql : g_kl) + base + 2 * p) = __halves2half2(l0, l1);
    }
}

// ---------------------------------------------------------------------------
// Kernel 2: rotate v and write TRANSPOSED [b][d][s] fp16 (hi only)
// ---------------------------------------------------------------------------
__global__ __launch_bounds__(256) void vrot_kernel(const float* __restrict__ Q,
                                                   const float* __restrict__ rot_w) {
    __shared__ __half th[64][33];
    int d0 = blockIdx.x * 64, s0 = blockIdx.y * 32, b = blockIdx.z;
    int tx = threadIdx.x, ty = threadIdx.y;
    int p = d0 / 2 + tx;
    float c = rot_w[2 * DD + 2 * p];
    float s = rot_w[2 * DD + 2 * p + 1];
    float inv = rsqrtf(c * c + s * s);
    c *= inv; s *= inv;
#pragma unroll
    for (int r = 0; r < 4; r++) {
        int srow = s0 + ty + 8 * r;
        float2 x = *(const float2*)(Q + ((size_t)b * SS + srow) * DD + d0 + 2 * tx);
        float y0 = c * x.x - s * x.y;
        float y1 = c * x.y + s * x.x;
        th[2 * tx][ty + 8 * r] = __float2half(y0);
        th[2 * tx + 1][ty + 8 * r] = __float2half(y1);
    }
    __syncthreads();
#pragma unroll
    for (int r = 0; r < 8; r++) {
        int d = r * 8 + ty;
        size_t o = ((size_t)b * DD + d0 + d) * SS + s0 + tx;
        g_vth[o] = th[d][tx];
    }
}

// ---------------------------------------------------------------------------
// Fused split-fp16 NT GEMM.
//   HAS_BL=true : C = Ah.Bh^T + Ah.Bl^T + Al.Bh^T   (QK)
//   HAS_BL=false: C = Ah.Bh^T + Al.Bh^T             (PV: (Ph+Pl).Vh)
// CTA tile 128x256, 8 warps (2m x 4n) of 64x64, K-chunk 32, 3-stage pipeline.
// Per-buffer smem layout (bytes): Ah@0 (10240), Al@10240, Bh@20480 (20480),
// [Bl@40960 (20480) if HAS_BL]. Buffer stride 61440 / 40960.
// ---------------------------------------------------------------------------
#define CHUNK 32
#define PAD 40
#define STAGES 3
#define QK_BUF 61440
#define PV_BUF 40960
#define QK_SMEM (STAGES * QK_BUF)
#define PV_SMEM (STAGES * PV_BUF)

template <bool HAS_BL>
__device__ __forceinline__ void load_tile_fused(
    const __half* gAh, const __half* gAl, const __half* gBh, const __half* gBl,
    int lda, int ldb, int kb, uint32_t s0, int tid) {
#pragma unroll
    for (int i = 0; i < 2; i++) {
        int lin = tid + i * 256;          // 0..511 : A rows 0..127 x 4 granules
        int row = lin >> 2;
        int g = lin & 3;
        uint32_t d = (uint32_t)(row * PAD + g * 8) * 2;
        cp_async16(s0 + d, gAh + (size_t)row * lda + kb + g * 8);
        cp_async16(s0 + 10240 + d, gAl + (size_t)row * lda + kb + g * 8);
    }
#pragma unroll
    for (int i = 0; i < 4; i++) {
        int lin = tid + i * 256;          // 0..1023 : B rows 0..255 x 4 granules
        int row = lin >> 2;
        int g = lin & 3;
        uint32_t d = (uint32_t)(row * PAD + g * 8) * 2;
        cp_async16(s0 + 20480 + d, gBh + (size_t)row * ldb + kb + g * 8);
        if (HAS_BL)
            cp_async16(s0 + 40960 + d, gBl + (size_t)row * ldb + kb + g * 8);
    }
}

template <bool HAS_BL>
__device__ __forceinline__ void gemm_fused_body(
    const __half* Ah, const __half* Al,
    const __half* Bh, const __half* Bl,
    int K, int lda, int ldb,
    size_t strideA, size_t strideB, size_t strideC,
    float* __restrict__ C, int ldc) {
    extern __shared__ __half sm[];
    uint32_t sbase = smem_u32(sm);
    const uint32_t BUF = HAS_BL ? QK_BUF : PV_BUF;

    int tid = threadIdx.x;
    int wid = tid >> 5, lid = tid & 31;
    int wm = wid & 1;      // 0..1  -> 64 rows each
    int wn = wid >> 1;     // 0..3  -> 64 cols each
    int b = blockIdx.z;
    int m0 = blockIdx.y * 128, n0 = blockIdx.x * 256;

    const __half* gAh = Ah + b * strideA + (size_t)m0 * lda;
    const __half* gAl = Al + b * strideA + (size_t)m0 * lda;
    const __half* gBh = Bh + b * strideB + (size_t)n0 * ldb;
    const __half* gBl = HAS_BL ? (Bl + b * strideB + (size_t)n0 * ldb) : gBh;

    uint32_t offA[4], offB[4];
#pragma unroll
    for (int am = 0; am < 4; am++)
        offA[am] = ((wm * 64 + am * 16 + (lid & 15)) * PAD + (lid >> 4) * 8) * 2;
#pragma unroll
    for (int bq = 0; bq < 4; bq++)
        offB[bq] = ((wn * 64 + bq * 16 + (lid & 7) + ((lid >> 4) << 3)) * PAD +
                    ((lid >> 3) & 1) * 8) * 2;

    float acc[4][8][4];
#pragma unroll
    for (int i = 0; i < 4; i++)
#pragma unroll
        for (int j = 0; j < 8; j++)
#pragma unroll
            for (int q = 0; q < 4; q++) acc[i][j][q] = 0.0f;

    int niter = K / CHUNK;
    load_tile_fused<HAS_BL>(gAh, gAl, gBh, gBl, lda, ldb, 0, sbase, tid);
    cp_commit();
    load_tile_fused<HAS_BL>(gAh, gAl, gBh, gBl, lda, ldb, CHUNK, sbase + BUF, tid);
    cp_commit();

    for (int it = 0; it < niter; it++) {
        if (it + 2 < niter)
            load_tile_fused<HAS_BL>(gAh, gAl, gBh, gBl, lda, ldb,
                                    (it + 2) * CHUNK,
                                    sbase + ((it + 2) % 3) * BUF, tid);
        cp_commit();          // one group per iteration (possibly empty)
        cp_wait<2>();
        __syncthreads();

        uint32_t sA = sbase + (it % 3) * BUF;
        uint32_t sAl_ = sA + 10240;
        uint32_t sBh_ = sA + 20480;
        uint32_t sBl_ = sA + 40960;

#pragma unroll
        for (int ks = 0; ks < 2; ks++) {
            uint32_t koff = ks * 32;   // 16 halves = 32 bytes
            uint32_t a[4][4], bh[8][2];
#pragma unroll
            for (int am = 0; am < 4; am++)
                ldsm_x4(a[am][0], a[am][1], a[am][2], a[am][3],
                        sA + offA[am] + koff);
#pragma unroll
            for (int bq = 0; bq < 4; bq++) {
                uint32_t r0, r1, r2, r3;
                ldsm_x4(r0, r1, r2, r3, sBh_ + offB[bq] + koff);
                bh[bq * 2][0] = r0; bh[bq * 2][1] = r1;
                bh[bq * 2 + 1][0] = r2; bh[bq * 2 + 1][1] = r3;
            }
            // term 1: Ah * Bh
#pragma unroll
            for (int am = 0; am < 4; am++)
#pragma unroll
                for (int bn = 0; bn < 8; bn++)
                    mma16816(acc[am][bn], a[am], bh[bn]);
            if (HAS_BL) {
                // term 2: Ah * Bl
                uint32_t bl[8][2];
#pragma unroll
                for (int bq = 0; bq < 4; bq++) {
                    uint32_t r0, r1, r2, r3;
                    ldsm_x4(r0, r1, r2, r3, sBl_ + offB[bq] + koff);
                    bl[bq * 2][0] = r0; bl[bq * 2][1] = r1;
                    bl[bq * 2 + 1][0] = r2; bl[bq * 2 + 1][1] = r3;
                }
#pragma unroll
                for (int am = 0; am < 4; am++)
#pragma unroll
                    for (int bn = 0; bn < 8; bn++)
                        mma16816(acc[am][bn], a[am], bl[bn]);
            }
            // term 3: Al * Bh (overwrite A frags with lo)
#pragma unroll
            for (int am = 0; am < 4; am++)
                ldsm_x4(a[am][0], a[am][1], a[am][2], a[am][3],
                        sAl_ + offA[am] + koff);
#pragma unroll
            for (int am = 0; am < 4; am++)
#pragma unroll
                for (int bn = 0; bn < 8; bn++)
                    mma16816(acc[am][bn], a[am], bh[bn]);
        }
        __syncthreads();
    }

    // epilogue
#pragma unroll
    for (int am = 0; am < 4; am++) {
        int row = m0 + wm * 64 + am * 16 + (lid >> 2);
#pragma unroll
        for (int bn = 0; bn < 8; bn++) {
            int col = n0 + wn * 64 + bn * 8 + (lid & 3) * 2;
            float* p0 = C + b * strideC + (size_t)row * ldc + col;
            float* p1 = C + b * strideC + (size_t)(row + 8) * ldc + col;
            *(float2*)p0 = make_float2(acc[am][bn][0], acc[am][bn][1]);
            *(float2*)p1 = make_float2(acc[am][bn][2], acc[am][bn][3]);
        }
    }
}

__global__ __launch_bounds__(256) void gemm_qk_kernel() {
    // scores = qh.kh + qh.kl + ql.kh
    gemm_fused_body<true>(g_qh, g_ql, g_kh, g_kl,
                          DD, DD, DD,
                          (size_t)SS * DD, (size_t)SS * DD, (size_t)SS * SS,
                          g_sc, SS);
}

__global__ __launch_bounds__(256) void gemm_pv_kernel(float* __restrict__ out) {
    // out = (ph + pl).vh   (B = v^T [D,S])
    gemm_fused_body<false>(g_ph, g_pl, g_vth, nullptr,
                           SS, SS, SS,
                           (size_t)SS * SS, (size_t)DD * SS, (size_t)SS * DD,
                           out, DD);
}

// ---------------------------------------------------------------------------
// Softmax((2+2x)/scale + bias) == softmax(2x/scale) (shift-invariant).
// Writes fp16 hi/lo split of probabilities. One block per row.
// ---------------------------------------------------------------------------
__global__ __launch_bounds__(256) void softmax_kernel(const float* __restrict__ scale) {
    size_t rowoff = (size_t)blockIdx.x * SS;
    const float* row = g_sc + rowoff;
    float alpha = 2.0f / scale[0];
    int tid = threadIdx.x;

    float vals[8];
    float lmax = -FLT_MAX;
#pragma unroll
    for (int i = 0; i < 8; i++) {
        float t = row[tid + i * 256] * alpha;
        vals[i] = t;
        lmax = fmaxf(lmax, t);
    }
    __shared__ float sred[8];
    __shared__ float sbc;
    float v = lmax;
#pragma unroll
    for (int o = 16; o > 0; o >>= 1) v = fmaxf(v, __shfl_xor_sync(0xffffffffu, v, o));
    if ((tid & 31) == 0) sred[tid >> 5] = v;
    __syncthreads();
    if (tid == 0) {
        float m = sred[0];
#pragma unroll
        for (int i = 1; i < 8; i++) m = fmaxf(m, sred[i]);
        sbc = m;
    }
    __syncthreads();
    float m = sbc;
    float lsum = 0.0f;
#pragma unroll
    for (int i = 0; i < 8; i++) {
        vals[i] = __expf(vals[i] - m);
        lsum += vals[i];
    }
    v = lsum;
#pragma unroll
    for (int o = 16; o > 0; o >>= 1) v += __shfl_xor_sync(0xffffffffu, v, o);
    __syncthreads();
    if ((tid & 31) == 0) sred[tid >> 5] = v;
    __syncthreads();
    if (tid == 0) {
        float t = 0.0f;
#pragma unroll
        for (int i = 0; i < 8; i++) t += sred[i];
        sbc = 1.0f / t;
    }
    __syncthreads();
    float inv = sbc;
#pragma unroll
    for (int i = 0; i < 8; i++) {
        float p = vals[i] * inv;
        __half h = __float2half(p);
        __half l = __float2half(p - __half2float(h));
        g_ph[rowoff + tid + i * 256] = h;
        g_pl[rowoff + tid + i * 256] = l;
    }
}

// ---------------------------------------------------------------------------
// Row L2 normalization of out rows (D=1024)
// ---------------------------------------------------------------------------
__global__ __launch_bounds__(256) void normalize_kernel(float* __restrict__ out) {
    float* row = out + (size_t)blockIdx.x * DD;
    int tid = threadIdx.x;
    float v[4];
    float ss = 0.0f;
#pragma unroll
    for (int i = 0; i < 4; i++) {
        v[i] = row[tid + i * 256];
        ss = fmaf(v[i], v[i], ss);
    }
    __shared__ float sred[8];
    __shared__ float sbc;
    float r = ss;
#pragma unroll
    for (int o = 16; o > 0; o >>= 1) r += __shfl_xor_sync(0xffffffffu, r, o);
    if ((tid & 31) == 0) sred[tid >> 5] = r;
    __syncthreads();
    if (tid == 0) {
        float t = 0.0f;
#pragma unroll
        for (int i = 0; i < 8; i++) t += sred[i];
        sbc = rsqrtf(fmaxf(fabsf(t), 1e-8f));
    }
    __syncthreads();
    float inv = sbc;
#pragma unroll
    for (int i = 0; i < 4; i++) row[tid + i * 256] = v[i] * inv;
}

// ---------------------------------------------------------------------------
extern "C" void kernel_launch(void* const* d_in, const int* in_sizes, int n_in,
                              void* d_out, int out_size) {
    (void)in_sizes; (void)n_in; (void)out_size;
    const float* Q     = (const float*)d_in[0];
    const float* rot_w = (const float*)d_in[1];
    const float* scale = (const float*)d_in[2];
    float* out = (float*)d_out;

    cudaFuncSetAttribute(gemm_qk_kernel,
                         cudaFuncAttributeMaxDynamicSharedMemorySize, QK_SMEM);
    cudaFuncSetAttribute(gemm_pv_kernel,
                         cudaFuncAttributeMaxDynamicSharedMemorySize, PV_SMEM);

    int pairs = BB * SS * (DD / 2);
    prep_kernel<<<(pairs + 255) / 256, 256>>>(Q, rot_w);
    vrot_kernel<<<dim3(DD / 64, SS / 32, BB), dim3(32, 8)>>>(Q, rot_w);

    gemm_qk_kernel<<<dim3(SS / 256, SS / 128, BB), 256, QK_SMEM>>>();
    softmax_kernel<<<BB * SS, 256>>>(scale);
    gemm_pv_kernel<<<dim3(DD / 256, SS / 128, BB), 256, PV_SMEM>>>(out);
    normalize_kernel<<<BB * SS, 256>>>(out);
}

// round 6
// speedup vs baseline: 4.6506x; 1.4526x over previous
#include <cuda_runtime.h>
#include <cuda_fp16.h>
#include <math.h>
#include <float.h>
#include <stdint.h>

#define BB 4
#define SS 2048
#define DD 1024

// ---------------------------------------------------------------------------
// Scratch (static device globals; runtime allocation is forbidden)
// ---------------------------------------------------------------------------
__device__ __half g_qh[BB * SS * DD];
__device__ __half g_ql[BB * SS * DD];
__device__ __half g_kh[BB * SS * DD];
__device__ __half g_vth[BB * DD * SS];          // v transposed [b][d][s], hi only
__device__ float  g_sc[(size_t)BB * SS * SS];   // raw scores
__device__ __half g_ph[(size_t)BB * SS * SS];   // softmax probs (fp16)

// ---------------------------------------------------------------------------
// PTX helpers (baseline ISA only — compute_103 safe)
// ---------------------------------------------------------------------------
__device__ __forceinline__ uint32_t smem_u32(const void* p) {
    uint32_t a;
    asm("{ .reg .u64 t; cvta.to.shared.u64 t, %1; cvt.u32.u64 %0, t; }"
        : "=r"(a) : "l"(p));
    return a;
}
__device__ __forceinline__ void cp_async16(uint32_t dst, const void* src) {
    asm volatile("cp.async.cg.shared.global [%0], [%1], 16;"
                 :: "r"(dst), "l"(src) : "memory");
}
__device__ __forceinline__ void cp_commit() {
    asm volatile("cp.async.commit_group;" ::: "memory");
}
template <int N>
__device__ __forceinline__ void cp_wait() {
    asm volatile("cp.async.wait_group %0;" :: "n"(N) : "memory");
}
__device__ __forceinline__ void ldsm_x4(uint32_t& r0, uint32_t& r1,
                                        uint32_t& r2, uint32_t& r3, uint32_t addr) {
    asm volatile("ldmatrix.sync.aligned.m8n8.x4.shared.b16 {%0,%1,%2,%3}, [%4];"
                 : "=r"(r0), "=r"(r1), "=r"(r2), "=r"(r3) : "r"(addr));
}
__device__ __forceinline__ void mma16816(float* c, const uint32_t* a, const uint32_t* b) {
    asm volatile(
        "mma.sync.aligned.m16n8k16.row.col.f32.f16.f16.f32 "
        "{%0,%1,%2,%3}, {%4,%5,%6,%7}, {%8,%9}, {%0,%1,%2,%3};"
        : "+f"(c[0]), "+f"(c[1]), "+f"(c[2]), "+f"(c[3])
        : "r"(a[0]), "r"(a[1]), "r"(a[2]), "r"(a[3]), "r"(b[0]), "r"(b[1]));
}

// ---------------------------------------------------------------------------
// Kernel 1: Givens-rotate Q into q (hi/lo) and k (hi only), layout [S, D]
// ---------------------------------------------------------------------------
__global__ void prep_kernel(const float* __restrict__ Q,
                            const float* __restrict__ rot_w) {
    int idx = blockIdx.x * blockDim.x + threadIdx.x;
    int total = BB * SS * (DD / 2);
    if (idx >= total) return;
    int p = idx % (DD / 2);
    size_t base = (size_t)(idx / (DD / 2)) * DD;
    float2 x = *(const float2*)(Q + base + 2 * p);
    // q: hi + lo
    {
        float c = rot_w[2 * p];
        float s = rot_w[2 * p + 1];
        float inv = rsqrtf(c * c + s * s);
        c *= inv; s *= inv;
        float y0 = c * x.x - s * x.y;
        float y1 = c * x.y + s * x.x;
        __half h0 = __float2half(y0), h1 = __float2half(y1);
        __half l0 = __float2half(y0 - __half2float(h0));
        __half l1 = __float2half(y1 - __half2float(h1));
        *(__half2*)(g_qh + base + 2 * p) = __halves2half2(h0, h1);
        *(__half2*)(g_ql + base + 2 * p) = __halves2half2(l0, l1);
    }
    // k: hi only
    {
        float c = rot_w[DD + 2 * p];
        float s = rot_w[DD + 2 * p + 1];
        float inv = rsqrtf(c * c + s * s);
        c *= inv; s *= inv;
        float y0 = c * x.x - s * x.y;
        float y1 = c * x.y + s * x.x;
        *(__half2*)(g_kh + base + 2 * p) =
            __halves2half2(__float2half(y0), __float2half(y1));
    }
}

// ---------------------------------------------------------------------------
// Kernel 2: rotate v and write TRANSPOSED [b][d][s] fp16 (hi only)
// ---------------------------------------------------------------------------
__global__ __launch_bounds__(256) void vrot_kernel(const float* __restrict__ Q,
                                                   const float* __restrict__ rot_w) {
    __shared__ __half th[64][33];
    int d0 = blockIdx.x * 64, s0 = blockIdx.y * 32, b = blockIdx.z;
    int tx = threadIdx.x, ty = threadIdx.y;
    int p = d0 / 2 + tx;
    float c = rot_w[2 * DD + 2 * p];
    float s = rot_w[2 * DD + 2 * p + 1];
    float inv = rsqrtf(c * c + s * s);
    c *= inv; s *= inv;
#pragma unroll
    for (int r = 0; r < 4; r++) {
        int srow = s0 + ty + 8 * r;
        float2 x = *(const float2*)(Q + ((size_t)b * SS + srow) * DD + d0 + 2 * tx);
        float y0 = c * x.x - s * x.y;
        float y1 = c * x.y + s * x.x;
        th[2 * tx][ty + 8 * r] = __float2half(y0);
        th[2 * tx + 1][ty + 8 * r] = __float2half(y1);
    }
    __syncthreads();
#pragma unroll
    for (int r = 0; r < 8; r++) {
        int d = r * 8 + ty;
        size_t o = ((size_t)b * DD + d0 + d) * SS + s0 + tx;
        g_vth[o] = th[d][tx];
    }
}

// ---------------------------------------------------------------------------
// Split-fp16 NT GEMM.
//   TERMS=2 : C = Ah.Bh^T + Al.Bh^T   (QK: (qh+ql).kh = q.kh)
//   TERMS=1 : C = Ah.Bh^T             (PV: ph.vh)
// CTA tile 128x256, 8 warps (2m x 4n) of 64x64, K-chunk 32, 3-stage pipeline.
// Per-buffer smem (bytes): Ah@0 (10240), [Al@10240 if TERMS=2], B@last (20480).
// ---------------------------------------------------------------------------
#define CHUNK 32
#define PAD 40
#define STAGES 3
#define QK_BUF 40960   // Ah + Al + Bh
#define PV_BUF 30720   // Ah + Bh
#define QK_SMEM (STAGES * QK_BUF)
#define PV_SMEM (STAGES * PV_BUF)

template <int TERMS>
__device__ __forceinline__ void load_tile_fused(
    const __half* gAh, const __half* gAl, const __half* gBh,
    int lda, int ldb, int kb, uint32_t s0, int tid) {
    const uint32_t BOFF = (TERMS == 2) ? 20480u : 10240u;
#pragma unroll
    for (int i = 0; i < 2; i++) {
        int lin = tid + i * 256;          // 0..511 : A rows 0..127 x 4 granules
        int row = lin >> 2;
        int g = lin & 3;
        uint32_t d = (uint32_t)(row * PAD + g * 8) * 2;
        cp_async16(s0 + d, gAh + (size_t)row * lda + kb + g * 8);
        if (TERMS == 2)
            cp_async16(s0 + 10240 + d, gAl + (size_t)row * lda + kb + g * 8);
    }
#pragma unroll
    for (int i = 0; i < 4; i++) {
        int lin = tid + i * 256;          // 0..1023 : B rows 0..255 x 4 granules
        int row = lin >> 2;
        int g = lin & 3;
        uint32_t d = (uint32_t)(row * PAD + g * 8) * 2;
        cp_async16(s0 + BOFF + d, gBh + (size_t)row * ldb + kb + g * 8);
    }
}

template <int TERMS>
__device__ __forceinline__ void gemm_fused_body(
    const __half* Ah, const __half* Al, const __half* Bh,
    int K, int lda, int ldb,
    size_t strideA, size_t strideB, size_t strideC,
    float* __restrict__ C, int ldc) {
    extern __shared__ __half sm[];
    uint32_t sbase = smem_u32(sm);
    const uint32_t BUF = (TERMS == 2) ? QK_BUF : PV_BUF;
    const uint32_t BOFF = (TERMS == 2) ? 20480u : 10240u;

    int tid = threadIdx.x;
    int wid = tid >> 5, lid = tid & 31;
    int wm = wid & 1;      // 0..1  -> 64 rows each
    int wn = wid >> 1;     // 0..3  -> 64 cols each
    int b = blockIdx.z;
    int m0 = blockIdx.y * 128, n0 = blockIdx.x * 256;

    const __half* gAh = Ah + b * strideA + (size_t)m0 * lda;
    const __half* gAl = (TERMS == 2) ? (Al + b * strideA + (size_t)m0 * lda) : gAh;
    const __half* gBh = Bh + b * strideB + (size_t)n0 * ldb;

    uint32_t offA[4], offB[4];
#pragma unroll
    for (int am = 0; am < 4; am++)
        offA[am] = ((wm * 64 + am * 16 + (lid & 15)) * PAD + (lid >> 4) * 8) * 2;
#pragma unroll
    for (int bq = 0; bq < 4; bq++)
        offB[bq] = ((wn * 64 + bq * 16 + (lid & 7) + ((lid >> 4) << 3)) * PAD +
                    ((lid >> 3) & 1) * 8) * 2;

    float acc[4][8][4];
#pragma unroll
    for (int i = 0; i < 4; i++)
#pragma unroll
        for (int j = 0; j < 8; j++)
#pragma unroll
            for (int q = 0; q < 4; q++) acc[i][j][q] = 0.0f;

    int niter = K / CHUNK;
    load_tile_fused<TERMS>(gAh, gAl, gBh, lda, ldb, 0, sbase, tid);
    cp_commit();
    load_tile_fused<TERMS>(gAh, gAl, gBh, lda, ldb, CHUNK, sbase + BUF, tid);
    cp_commit();

    for (int it = 0; it < niter; it++) {
        if (it + 2 < niter)
            load_tile_fused<TERMS>(gAh, gAl, gBh, lda, ldb, (it + 2) * CHUNK,
                                   sbase + ((it + 2) % 3) * BUF, tid);
        cp_commit();          // one group per iteration (possibly empty)
        cp_wait<2>();
        __syncthreads();

        uint32_t sA = sbase + (it % 3) * BUF;
        uint32_t sAl_ = sA + 10240;
        uint32_t sBh_ = sA + BOFF;

#pragma unroll
        for (int ks = 0; ks < 2; ks++) {
            uint32_t koff = ks * 32;   // 16 halves = 32 bytes
            uint32_t a[4][4], bh[8][2];
#pragma unroll
            for (int am = 0; am < 4; am++)
                ldsm_x4(a[am][0], a[am][1], a[am][2], a[am][3],
                        sA + offA[am] + koff);
#pragma unroll
            for (int bq = 0; bq < 4; bq++) {
                uint32_t r0, r1, r2, r3;
                ldsm_x4(r0, r1, r2, r3, sBh_ + offB[bq] + koff);
                bh[bq * 2][0] = r0; bh[bq * 2][1] = r1;
                bh[bq * 2 + 1][0] = r2; bh[bq * 2 + 1][1] = r3;
            }
            // term 1: Ah * Bh
#pragma unroll
            for (int am = 0; am < 4; am++)
#pragma unroll
                for (int bn = 0; bn < 8; bn++)
                    mma16816(acc[am][bn], a[am], bh[bn]);
            if (TERMS == 2) {
                // term 2: Al * Bh (overwrite A frags with lo)
#pragma unroll
                for (int am = 0; am < 4; am++)
                    ldsm_x4(a[am][0], a[am][1], a[am][2], a[am][3],
                            sAl_ + offA[am] + koff);
#pragma unroll
                for (int am = 0; am < 4; am++)
#pragma unroll
                    for (int bn = 0; bn < 8; bn++)
                        mma16816(acc[am][bn], a[am], bh[bn]);
            }
        }
        __syncthreads();
    }

    // epilogue
#pragma unroll
    for (int am = 0; am < 4; am++) {
        int row = m0 + wm * 64 + am * 16 + (lid >> 2);
#pragma unroll
        for (int bn = 0; bn < 8; bn++) {
            int col = n0 + wn * 64 + bn * 8 + (lid & 3) * 2;
            float* p0 = C + b * strideC + (size_t)row * ldc + col;
            float* p1 = C + b * strideC + (size_t)(row + 8) * ldc + col;
            *(float2*)p0 = make_float2(acc[am][bn][0], acc[am][bn][1]);
            *(float2*)p1 = make_float2(acc[am][bn][2], acc[am][bn][3]);
        }
    }
}

__global__ __launch_bounds__(256) void gemm_qk_kernel() {
    // scores = (qh + ql).kh = q.kh
    gemm_fused_body<2>(g_qh, g_ql, g_kh,
                       DD, DD, DD,
                       (size_t)SS * DD, (size_t)SS * DD, (size_t)SS * SS,
                       g_sc, SS);
}

__global__ __launch_bounds__(256) void gemm_pv_kernel(float* __restrict__ out) {
    // out = ph.vh   (B = v^T [D,S])
    gemm_fused_body<1>(g_ph, nullptr, g_vth,
                       SS, SS, SS,
                       (size_t)SS * SS, (size_t)DD * SS, (size_t)SS * DD,
                       out, DD);
}

// ---------------------------------------------------------------------------
// Softmax((2+2x)/scale + bias) == softmax(2x/scale) (shift-invariant).
// Writes fp16 probabilities. One block per row.
// ---------------------------------------------------------------------------
__global__ __launch_bounds__(256) void softmax_kernel(const float* __restrict__ scale) {
    size_t rowoff = (size_t)blockIdx.x * SS;
    const float* row = g_sc + rowoff;
    float alpha = 2.0f / scale[0];
    int tid = threadIdx.x;

    float vals[8];
    float lmax = -FLT_MAX;
#pragma unroll
    for (int i = 0; i < 8; i++) {
        float t = row[tid + i * 256] * alpha;
        vals[i] = t;
        lmax = fmaxf(lmax, t);
    }
    __shared__ float sred[8];
    __shared__ float sbc;
    float v = lmax;
#pragma unroll
    for (int o = 16; o > 0; o >>= 1) v = fmaxf(v, __shfl_xor_sync(0xffffffffu, v, o));
    if ((tid & 31) == 0) sred[tid >> 5] = v;
    __syncthreads();
    if (tid == 0) {
        float m = sred[0];
#pragma unroll
        for (int i = 1; i < 8; i++) m = fmaxf(m, sred[i]);
        sbc = m;
    }
    __syncthreads();
    float m = sbc;
    float lsum = 0.0f;
#pragma unroll
    for (int i = 0; i < 8; i++) {
        vals[i] = __expf(vals[i] - m);
        lsum += vals[i];
    }
    v = lsum;
#pragma unroll
    for (int o = 16; o > 0; o >>= 1) v += __shfl_xor_sync(0xffffffffu, v, o);
    __syncthreads();
    if ((tid & 31) == 0) sred[tid >> 5] = v;
    __syncthreads();
    if (tid == 0) {
        float t = 0.0f;
#pragma unroll
        for (int i = 0; i < 8; i++) t += sred[i];
        sbc = 1.0f / t;
    }
    __syncthreads();
    float inv = sbc;
#pragma unroll
    for (int i = 0; i < 8; i++)
        g_ph[rowoff + tid + i * 256] = __float2half(vals[i] * inv);
}

// ---------------------------------------------------------------------------
// Row L2 normalization of out rows (D=1024)
// ---------------------------------------------------------------------------
__global__ __launch_bounds__(256) void normalize_kernel(float* __restrict__ out) {
    float* row = out + (size_t)blockIdx.x * DD;
    int tid = threadIdx.x;
    float v[4];
    float ss = 0.0f;
#pragma unroll
    for (int i = 0; i < 4; i++) {
        v[i] = row[tid + i * 256];
        ss = fmaf(v[i], v[i], ss);
    }
    __shared__ float sred[8];
    __shared__ float sbc;
    float r = ss;
#pragma unroll
    for (int o = 16; o > 0; o >>= 1) r += __shfl_xor_sync(0xffffffffu, r, o);
    if ((tid & 31) == 0) sred[tid >> 5] = r;
    __syncthreads();
    if (tid == 0) {
        float t = 0.0f;
#pragma unroll
        for (int i = 0; i < 8; i++) t += sred[i];
        sbc = rsqrtf(fmaxf(fabsf(t), 1e-8f));
    }
    __syncthreads();
    float inv = sbc;
#pragma unroll
    for (int i = 0; i < 4; i++) row[tid + i * 256] = v[i] * inv;
}

// ---------------------------------------------------------------------------
extern "C" void kernel_launch(void* const* d_in, const int* in_sizes, int n_in,
                              void* d_out, int out_size) {
    (void)in_sizes; (void)n_in; (void)out_size;
    const float* Q     = (const float*)d_in[0];
    const float* rot_w = (const float*)d_in[1];
    const float* scale = (const float*)d_in[2];
    float* out = (float*)d_out;

    cudaFuncSetAttribute(gemm_qk_kernel,
                         cudaFuncAttributeMaxDynamicSharedMemorySize, QK_SMEM);
    cudaFuncSetAttribute(gemm_pv_kernel,
                         cudaFuncAttributeMaxDynamicSharedMemorySize, PV_SMEM);

    int pairs = BB * SS * (DD / 2);
    prep_kernel<<<(pairs + 255) / 256, 256>>>(Q, rot_w);
    vrot_kernel<<<dim3(DD / 64, SS / 32, BB), dim3(32, 8)>>>(Q, rot_w);

    gemm_qk_kernel<<<dim3(SS / 256, SS / 128, BB), 256, QK_SMEM>>>();
    softmax_kernel<<<BB * SS, 256>>>(scale);
    gemm_pv_kernel<<<dim3(DD / 256, SS / 128, BB), 256, PV_SMEM>>>(out);
    normalize_kernel<<<BB * SS, 256>>>(out);
}